// round 6
// baseline (speedup 1.0000x reference)
#include <cuda_runtime.h>
#include <math.h>

#define N_NODES 50000
#define N_EDGES 800000
#define F 128
#define TM 64
#define TK 32

typedef unsigned long long u64;

// Scratch (allocation-free rule: __device__ globals)
__device__ float g_h[N_NODES * F];      // feat @ W_pool^T + b_pool
__device__ float g_WpT[F * F];          // W_pool transposed: [k][c]
__device__ float g_WsT[F * F];          // W_self transposed: [k][c]
__device__ int   g_count[N_NODES];      // in-degree histogram
__device__ int   g_off[N_NODES + 1];    // CSR row offsets (by dst)
__device__ int   g_cursor[N_NODES];     // scatter cursors (init = offsets)
__device__ int2  g_edges[N_EDGES];      // dst-sorted records: {src, bits(w)}

// ---- packed f32x2 helpers (Blackwell sm_103a; ptxas never auto-fuses) ----
__device__ __forceinline__ u64 pack2(float lo, float hi) {
    u64 r; asm("mov.b64 %0, {%1, %2};" : "=l"(r) : "f"(lo), "f"(hi)); return r;
}
__device__ __forceinline__ u64 fma2(u64 a, u64 b, u64 c) {
    u64 d; asm("fma.rn.f32x2 %0, %1, %2, %3;" : "=l"(d) : "l"(a), "l"(b), "l"(c));
    return d;
}
__device__ __forceinline__ void unpack2(u64 v, float& lo, float& hi) {
    asm("mov.b64 {%0, %1}, %2;" : "=f"(lo), "=f"(hi) : "l"(v));
}

// ---------------------------------------------------------------------------
// Zero histogram + transpose weights (runs every launch; deterministic)
// ---------------------------------------------------------------------------
__global__ void zero_transpose_kernel(const float* __restrict__ Wp,
                                      const float* __restrict__ Ws) {
    int i = blockIdx.x * blockDim.x + threadIdx.x;
    if (i < N_NODES) g_count[i] = 0;
    if (i < F * F) {
        int c = i >> 7;
        int k = i & (F - 1);
        g_WpT[k * F + c] = Wp[c * F + k];
        g_WsT[k * F + c] = Ws[c * F + k];
    }
}

// ---------------------------------------------------------------------------
// In-degree histogram
// ---------------------------------------------------------------------------
__global__ void hist_kernel(const int* __restrict__ dst) {
    int e = blockIdx.x * blockDim.x + threadIdx.x;
    if (e < N_EDGES) atomicAdd(&g_count[dst[e]], 1);
}

// ---------------------------------------------------------------------------
// Single-block exclusive scan of g_count -> g_off, g_cursor
// 1024 threads, each owns a contiguous chunk of ~49 counters.
// ---------------------------------------------------------------------------
__global__ __launch_bounds__(1024) void scan_kernel() {
    const int CHUNK = (N_NODES + 1023) / 1024;   // 49
    __shared__ int warp_sums[32];
    int tid  = threadIdx.x;
    int base = tid * CHUNK;
    int hi   = min(base + CHUNK, N_NODES);

    int sum = 0;
    for (int i = base; i < hi; i++) sum += g_count[i];

    // exclusive scan of per-thread sums across the block
    int lane = tid & 31, wid = tid >> 5;
    int v = sum;
#pragma unroll
    for (int o = 1; o < 32; o <<= 1) {
        int t = __shfl_up_sync(0xffffffff, v, o);
        if (lane >= o) v += t;
    }
    if (lane == 31) warp_sums[wid] = v;
    __syncthreads();
    if (wid == 0) {
        int wv = warp_sums[lane];
#pragma unroll
        for (int o = 1; o < 32; o <<= 1) {
            int t = __shfl_up_sync(0xffffffff, wv, o);
            if (lane >= o) wv += t;
        }
        warp_sums[lane] = wv;
    }
    __syncthreads();
    int excl = v - sum + (wid > 0 ? warp_sums[wid - 1] : 0);

    int run = excl;
    for (int i = base; i < hi; i++) {
        g_off[i]    = run;
        g_cursor[i] = run;
        run += g_count[i];
    }
    if (tid == 0) g_off[N_NODES] = N_EDGES;
}

// ---------------------------------------------------------------------------
// Scatter packed edge records into dst-sorted order
// ---------------------------------------------------------------------------
__global__ void scatter_kernel(const float* __restrict__ efeat,
                               const int* __restrict__ src,
                               const int* __restrict__ dst) {
    int e = blockIdx.x * blockDim.x + threadIdx.x;
    if (e < N_EDGES) {
        int d = dst[e];
        int pos = atomicAdd(&g_cursor[d], 1);
        g_edges[pos] = make_int2(src[e], __float_as_int(efeat[e]));
    }
}

// ---------------------------------------------------------------------------
// Dual GEMM with packed fp32x2 FMAs:
//   h   = feat @ Wp^T + bp  (to g_h)
//   out = feat @ Ws^T + bs  (to d_out)
// ---------------------------------------------------------------------------
__global__ __launch_bounds__(256, 2) void gemm_dual(const float* __restrict__ feat,
                                                    const float* __restrict__ bp,
                                                    const float* __restrict__ bs,
                                                    float* __restrict__ out) {
    __shared__ float As[TM][TK + 4];
    __shared__ float Wps[TK][F];
    __shared__ float Wss[TK][F];

    int tid  = threadIdx.x;
    int row0 = blockIdx.x * TM;
    int tr   = tid >> 4;
    int tc   = tid & 15;

    u64 accP[4][4];
    u64 accS[4][4];
    const u64 z = pack2(0.f, 0.f);
#pragma unroll
    for (int r = 0; r < 4; r++)
#pragma unroll
        for (int c = 0; c < 4; c++) { accP[r][c] = z; accS[r][c] = z; }

    for (int kt = 0; kt < F; kt += TK) {
#pragma unroll
        for (int j = 0; j < 2; j++) {
            int f4 = tid + j * 256;
            int r  = f4 >> 3;
            int k4 = f4 & 7;
            int gr = row0 + r;
            float4 v = make_float4(0.f, 0.f, 0.f, 0.f);
            if (gr < N_NODES)
                v = *(const float4*)&feat[gr * F + kt + k4 * 4];
            *(float4*)&As[r][k4 * 4] = v;
        }
#pragma unroll
        for (int j = 0; j < 4; j++) {
            int f4 = tid + j * 256;
            int k  = f4 >> 5;
            int c4 = f4 & 31;
            *(float4*)&Wps[k][c4 * 4] = *(const float4*)&g_WpT[(kt + k) * F + c4 * 4];
            *(float4*)&Wss[k][c4 * 4] = *(const float4*)&g_WsT[(kt + k) * F + c4 * 4];
        }
        __syncthreads();

#pragma unroll
        for (int kk = 0; kk < TK; kk++) {
            u64 a[4];
#pragma unroll
            for (int r = 0; r < 4; r++) {
                float av = As[tr * 4 + r][kk];
                a[r] = pack2(av, av);
            }
            ulonglong2 p0 = *(const ulonglong2*)&Wps[kk][tc * 4];
            ulonglong2 p1 = *(const ulonglong2*)&Wps[kk][64 + tc * 4];
            ulonglong2 s0 = *(const ulonglong2*)&Wss[kk][tc * 4];
            ulonglong2 s1 = *(const ulonglong2*)&Wss[kk][64 + tc * 4];
#pragma unroll
            for (int r = 0; r < 4; r++) {
                accP[r][0] = fma2(a[r], p0.x, accP[r][0]);
                accP[r][1] = fma2(a[r], p0.y, accP[r][1]);
                accP[r][2] = fma2(a[r], p1.x, accP[r][2]);
                accP[r][3] = fma2(a[r], p1.y, accP[r][3]);
                accS[r][0] = fma2(a[r], s0.x, accS[r][0]);
                accS[r][1] = fma2(a[r], s0.y, accS[r][1]);
                accS[r][2] = fma2(a[r], s1.x, accS[r][2]);
                accS[r][3] = fma2(a[r], s1.y, accS[r][3]);
            }
        }
        __syncthreads();
    }

    int c0 = tc * 4;
    int c1 = 64 + tc * 4;
    float4 bpv0 = *(const float4*)&bp[c0];
    float4 bpv1 = *(const float4*)&bp[c1];
    float4 bsv0 = *(const float4*)&bs[c0];
    float4 bsv1 = *(const float4*)&bs[c1];
#pragma unroll
    for (int r = 0; r < 4; r++) {
        int gr = row0 + tr * 4 + r;
        if (gr < N_NODES) {
            float4 hp0, hp1, os0, os1;
            unpack2(accP[r][0], hp0.x, hp0.y);
            unpack2(accP[r][1], hp0.z, hp0.w);
            unpack2(accP[r][2], hp1.x, hp1.y);
            unpack2(accP[r][3], hp1.z, hp1.w);
            unpack2(accS[r][0], os0.x, os0.y);
            unpack2(accS[r][1], os0.z, os0.w);
            unpack2(accS[r][2], os1.x, os1.y);
            unpack2(accS[r][3], os1.z, os1.w);
            hp0.x += bpv0.x; hp0.y += bpv0.y; hp0.z += bpv0.z; hp0.w += bpv0.w;
            hp1.x += bpv1.x; hp1.y += bpv1.y; hp1.z += bpv1.z; hp1.w += bpv1.w;
            os0.x += bsv0.x; os0.y += bsv0.y; os0.z += bsv0.z; os0.w += bsv0.w;
            os1.x += bsv1.x; os1.y += bsv1.y; os1.z += bsv1.z; os1.w += bsv1.w;
            *(float4*)&g_h[gr * F + c0] = hp0;
            *(float4*)&g_h[gr * F + c1] = hp1;
            *(float4*)&out[gr * F + c0] = os0;
            *(float4*)&out[gr * F + c1] = os1;
        }
    }
}

// ---------------------------------------------------------------------------
// Aggregation: warp per destination node, gather-only (no atomics).
// Lane l owns 4 features. wsum by warp-reduce; edge loop processes 2 edges
// per iteration with all loads issued before use (MLP ~4/warp).
// ---------------------------------------------------------------------------
__global__ __launch_bounds__(256) void agg_kernel(float* __restrict__ out) {
    int node = (blockIdx.x * blockDim.x + threadIdx.x) >> 5;
    int lane = threadIdx.x & 31;
    if (node >= N_NODES) return;

    int e0 = g_off[node];
    int e1 = g_off[node + 1];
    int deg = e1 - e0;
    if (deg == 0) return;   // agg contributes 0 (matches max(deg,1) semantics)

    // wsum: lane-parallel over edges, warp reduce
    float ws = 0.f;
    for (int e = e0 + lane; e < e1; e += 32)
        ws += __int_as_float(__ldg(&g_edges[e].y));
#pragma unroll
    for (int o = 16; o > 0; o >>= 1)
        ws += __shfl_xor_sync(0xffffffff, ws, o);

    float inv_ws  = __fdividef(1.0f, ws);
    float inv_deg = __fdividef(1.0f, (float)deg);

    float4 acc0 = make_float4(0.f, 0.f, 0.f, 0.f);
    float4 acc1 = make_float4(0.f, 0.f, 0.f, 0.f);
    int e = e0;
    // 2 edges per iteration: issue both records + both h-row gathers up front
    for (; e + 1 < e1; e += 2) {
        int2 ra = __ldg(&g_edges[e]);
        int2 rb = __ldg(&g_edges[e + 1]);
        const float4 va = *(const float4*)&g_h[ra.x * F + lane * 4];
        const float4 vb = *(const float4*)&g_h[rb.x * F + lane * 4];
        float ma = __expf(-__int_as_float(ra.y) * inv_ws);
        float mb = __expf(-__int_as_float(rb.y) * inv_ws);
        acc0.x = fmaf(ma, va.x, acc0.x);
        acc0.y = fmaf(ma, va.y, acc0.y);
        acc0.z = fmaf(ma, va.z, acc0.z);
        acc0.w = fmaf(ma, va.w, acc0.w);
        acc1.x = fmaf(mb, vb.x, acc1.x);
        acc1.y = fmaf(mb, vb.y, acc1.y);
        acc1.z = fmaf(mb, vb.z, acc1.z);
        acc1.w = fmaf(mb, vb.w, acc1.w);
    }
    if (e < e1) {
        int2 rec = __ldg(&g_edges[e]);
        float m = __expf(-__int_as_float(rec.y) * inv_ws);
        float4 v = *(const float4*)&g_h[rec.x * F + lane * 4];
        acc0.x = fmaf(m, v.x, acc0.x);
        acc0.y = fmaf(m, v.y, acc0.y);
        acc0.z = fmaf(m, v.z, acc0.z);
        acc0.w = fmaf(m, v.w, acc0.w);
    }
    acc0.x += acc1.x; acc0.y += acc1.y; acc0.z += acc1.z; acc0.w += acc1.w;

    float4 o = *(const float4*)&out[node * F + lane * 4];
    o.x += acc0.x * inv_deg;
    o.y += acc0.y * inv_deg;
    o.z += acc0.z * inv_deg;
    o.w += acc0.w * inv_deg;
    *(float4*)&out[node * F + lane * 4] = o;
}

// ---------------------------------------------------------------------------
extern "C" void kernel_launch(void* const* d_in, const int* in_sizes, int n_in,
                              void* d_out, int out_size) {
    const float* feat  = (const float*)d_in[0];
    const float* efeat = (const float*)d_in[1];
    const int*   src   = (const int*)d_in[2];
    const int*   dst   = (const int*)d_in[3];
    const float* Wp    = (const float*)d_in[4];
    const float* bp    = (const float*)d_in[5];
    const float* Ws    = (const float*)d_in[6];
    const float* bs    = (const float*)d_in[7];
    float* out = (float*)d_out;

    zero_transpose_kernel<<<(N_NODES + 255) / 256, 256>>>(Wp, Ws);
    hist_kernel<<<(N_EDGES + 255) / 256, 256>>>(dst);
    scan_kernel<<<1, 1024>>>();
    scatter_kernel<<<(N_EDGES + 255) / 256, 256>>>(efeat, src, dst);
    gemm_dual<<<(N_NODES + TM - 1) / TM, 256>>>(feat, bp, bs, out);
    agg_kernel<<<(N_NODES * 32 + 255) / 256, 256>>>(out);
}

// round 8
// speedup vs baseline: 1.0285x; 1.0285x over previous
#include <cuda_runtime.h>
#include <cuda_fp16.h>
#include <math.h>

#define N_NODES 50000
#define N_EDGES 800000
#define F 128
#define TM 64
#define TK 32

typedef unsigned long long u64;

// Scratch (allocation-free rule: __device__ globals)
__device__ __half2 g_hh[N_NODES * (F / 2)];  // h = feat@Wp^T+bp, fp16 pairs
__device__ float g_WpT[F * F];          // W_pool transposed: [k][c]
__device__ float g_WsT[F * F];          // W_self transposed: [k][c]
__device__ int   g_count[N_NODES];      // in-degree histogram
__device__ int   g_off[N_NODES + 1];    // CSR row offsets (by dst)
__device__ int   g_cursor[N_NODES];     // scatter cursors (init = offsets)
__device__ int2  g_edges[N_EDGES];      // dst-sorted records: {src, bits(w)}

// ---- packed f32x2 helpers (Blackwell sm_103a; ptxas never auto-fuses) ----
__device__ __forceinline__ u64 pack2(float lo, float hi) {
    u64 r; asm("mov.b64 %0, {%1, %2};" : "=l"(r) : "f"(lo), "f"(hi)); return r;
}
__device__ __forceinline__ u64 fma2(u64 a, u64 b, u64 c) {
    u64 d; asm("fma.rn.f32x2 %0, %1, %2, %3;" : "=l"(d) : "l"(a), "l"(b), "l"(c));
    return d;
}
__device__ __forceinline__ void unpack2(u64 v, float& lo, float& hi) {
    asm("mov.b64 {%0, %1}, %2;" : "=f"(lo), "=f"(hi) : "l"(v));
}

// ---------------------------------------------------------------------------
// Zero histogram + transpose weights (runs every launch; deterministic)
// ---------------------------------------------------------------------------
__global__ void zero_transpose_kernel(const float* __restrict__ Wp,
                                      const float* __restrict__ Ws) {
    int i = blockIdx.x * blockDim.x + threadIdx.x;
    if (i < N_NODES) g_count[i] = 0;
    if (i < F * F) {
        int c = i >> 7;
        int k = i & (F - 1);
        g_WpT[k * F + c] = Wp[c * F + k];
        g_WsT[k * F + c] = Ws[c * F + k];
    }
}

// ---------------------------------------------------------------------------
// In-degree histogram
// ---------------------------------------------------------------------------
__global__ void hist_kernel(const int* __restrict__ dst) {
    int e = blockIdx.x * blockDim.x + threadIdx.x;
    if (e < N_EDGES) atomicAdd(&g_count[dst[e]], 1);
}

// ---------------------------------------------------------------------------
// Single-block exclusive scan of g_count -> g_off, g_cursor
// ---------------------------------------------------------------------------
__global__ __launch_bounds__(1024) void scan_kernel() {
    const int CHUNK = (N_NODES + 1023) / 1024;   // 49
    __shared__ int warp_sums[32];
    int tid  = threadIdx.x;
    int base = tid * CHUNK;
    int hi   = min(base + CHUNK, N_NODES);

    int sum = 0;
    for (int i = base; i < hi; i++) sum += g_count[i];

    int lane = tid & 31, wid = tid >> 5;
    int v = sum;
#pragma unroll
    for (int o = 1; o < 32; o <<= 1) {
        int t = __shfl_up_sync(0xffffffff, v, o);
        if (lane >= o) v += t;
    }
    if (lane == 31) warp_sums[wid] = v;
    __syncthreads();
    if (wid == 0) {
        int wv = warp_sums[lane];
#pragma unroll
        for (int o = 1; o < 32; o <<= 1) {
            int t = __shfl_up_sync(0xffffffff, wv, o);
            if (lane >= o) wv += t;
        }
        warp_sums[lane] = wv;
    }
    __syncthreads();
    int excl = v - sum + (wid > 0 ? warp_sums[wid - 1] : 0);

    int run = excl;
    for (int i = base; i < hi; i++) {
        g_off[i]    = run;
        g_cursor[i] = run;
        run += g_count[i];
    }
    if (tid == 0) g_off[N_NODES] = N_EDGES;
}

// ---------------------------------------------------------------------------
// Scatter packed edge records into dst-sorted order
// ---------------------------------------------------------------------------
__global__ void scatter_kernel(const float* __restrict__ efeat,
                               const int* __restrict__ src,
                               const int* __restrict__ dst) {
    int e = blockIdx.x * blockDim.x + threadIdx.x;
    if (e < N_EDGES) {
        int d = dst[e];
        int pos = atomicAdd(&g_cursor[d], 1);
        g_edges[pos] = make_int2(src[e], __float_as_int(efeat[e]));
    }
}

// ---------------------------------------------------------------------------
// Dual GEMM with packed fp32x2 FMAs:
//   h   = feat @ Wp^T + bp  (fp16 -> g_hh)
//   out = feat @ Ws^T + bs  (fp32 -> d_out)
// A staged pre-duplicated as float2 (v,v): LDS.64 yields the packed FMA2
// operand directly -> no per-kk pack movs.
// ---------------------------------------------------------------------------
__global__ __launch_bounds__(256, 2) void gemm_dual(const float* __restrict__ feat,
                                                    const float* __restrict__ bp,
                                                    const float* __restrict__ bs,
                                                    float* __restrict__ out) {
    __shared__ float2 As2[TM][TK + 2];   // duplicated pairs, row stride 272B
    __shared__ float Wps[TK][F];
    __shared__ float Wss[TK][F];

    int tid  = threadIdx.x;
    int row0 = blockIdx.x * TM;
    int tr   = tid >> 4;
    int tc   = tid & 15;

    u64 accP[4][4];
    u64 accS[4][4];
    const u64 z = pack2(0.f, 0.f);
#pragma unroll
    for (int r = 0; r < 4; r++)
#pragma unroll
        for (int c = 0; c < 4; c++) { accP[r][c] = z; accS[r][c] = z; }

    for (int kt = 0; kt < F; kt += TK) {
#pragma unroll
        for (int j = 0; j < 2; j++) {
            int f4 = tid + j * 256;
            int r  = f4 >> 3;
            int k4 = f4 & 7;
            int gr = row0 + r;
            float4 v = make_float4(0.f, 0.f, 0.f, 0.f);
            if (gr < N_NODES)
                v = *(const float4*)&feat[gr * F + kt + k4 * 4];
            As2[r][k4 * 4 + 0] = make_float2(v.x, v.x);
            As2[r][k4 * 4 + 1] = make_float2(v.y, v.y);
            As2[r][k4 * 4 + 2] = make_float2(v.z, v.z);
            As2[r][k4 * 4 + 3] = make_float2(v.w, v.w);
        }
#pragma unroll
        for (int j = 0; j < 4; j++) {
            int f4 = tid + j * 256;
            int k  = f4 >> 5;
            int c4 = f4 & 31;
            *(float4*)&Wps[k][c4 * 4] = *(const float4*)&g_WpT[(kt + k) * F + c4 * 4];
            *(float4*)&Wss[k][c4 * 4] = *(const float4*)&g_WsT[(kt + k) * F + c4 * 4];
        }
        __syncthreads();

#pragma unroll
        for (int kk = 0; kk < TK; kk++) {
            u64 a[4];
#pragma unroll
            for (int r = 0; r < 4; r++)
                a[r] = *(const u64*)&As2[tr * 4 + r][kk];   // LDS.64 pre-packed
            ulonglong2 p0 = *(const ulonglong2*)&Wps[kk][tc * 4];
            ulonglong2 p1 = *(const ulonglong2*)&Wps[kk][64 + tc * 4];
            ulonglong2 s0 = *(const ulonglong2*)&Wss[kk][tc * 4];
            ulonglong2 s1 = *(const ulonglong2*)&Wss[kk][64 + tc * 4];
#pragma unroll
            for (int r = 0; r < 4; r++) {
                accP[r][0] = fma2(a[r], p0.x, accP[r][0]);
                accP[r][1] = fma2(a[r], p0.y, accP[r][1]);
                accP[r][2] = fma2(a[r], p1.x, accP[r][2]);
                accP[r][3] = fma2(a[r], p1.y, accP[r][3]);
                accS[r][0] = fma2(a[r], s0.x, accS[r][0]);
                accS[r][1] = fma2(a[r], s0.y, accS[r][1]);
                accS[r][2] = fma2(a[r], s1.x, accS[r][2]);
                accS[r][3] = fma2(a[r], s1.y, accS[r][3]);
            }
        }
        __syncthreads();
    }

    int c0 = tc * 4;
    int c1 = 64 + tc * 4;
    float4 bpv0 = *(const float4*)&bp[c0];
    float4 bpv1 = *(const float4*)&bp[c1];
    float4 bsv0 = *(const float4*)&bs[c0];
    float4 bsv1 = *(const float4*)&bs[c1];
#pragma unroll
    for (int r = 0; r < 4; r++) {
        int gr = row0 + tr * 4 + r;
        if (gr < N_NODES) {
            float4 hp0, hp1, os0, os1;
            unpack2(accP[r][0], hp0.x, hp0.y);
            unpack2(accP[r][1], hp0.z, hp0.w);
            unpack2(accP[r][2], hp1.x, hp1.y);
            unpack2(accP[r][3], hp1.z, hp1.w);
            unpack2(accS[r][0], os0.x, os0.y);
            unpack2(accS[r][1], os0.z, os0.w);
            unpack2(accS[r][2], os1.x, os1.y);
            unpack2(accS[r][3], os1.z, os1.w);
            hp0.x += bpv0.x; hp0.y += bpv0.y; hp0.z += bpv0.z; hp0.w += bpv0.w;
            hp1.x += bpv1.x; hp1.y += bpv1.y; hp1.z += bpv1.z; hp1.w += bpv1.w;
            os0.x += bsv0.x; os0.y += bsv0.y; os0.z += bsv0.z; os0.w += bsv0.w;
            os1.x += bsv1.x; os1.y += bsv1.y; os1.z += bsv1.z; os1.w += bsv1.w;

            // h -> fp16 pairs (8B per 4 features)
            __half2 ha = __float22half2_rn(make_float2(hp0.x, hp0.y));
            __half2 hb = __float22half2_rn(make_float2(hp0.z, hp0.w));
            __half2 hc = __float22half2_rn(make_float2(hp1.x, hp1.y));
            __half2 hd = __float22half2_rn(make_float2(hp1.z, hp1.w));
            uint2 u0, u1;
            u0.x = *(unsigned int*)&ha;  u0.y = *(unsigned int*)&hb;
            u1.x = *(unsigned int*)&hc;  u1.y = *(unsigned int*)&hd;
            *(uint2*)&g_hh[gr * (F / 2) + tc * 2]      = u0;
            *(uint2*)&g_hh[gr * (F / 2) + 32 + tc * 2] = u1;

            *(float4*)&out[gr * F + c0] = os0;
            *(float4*)&out[gr * F + c1] = os1;
        }
    }
}

// ---------------------------------------------------------------------------
// Aggregation: warp per destination node, gather-only (no atomics).
// fp16 gather (8B/lane/edge) with fp32 register accumulation.
// 4 edges per iteration: all 8 loads issued before any use (MLP ~8/warp).
// ---------------------------------------------------------------------------
__global__ __launch_bounds__(256) void agg_kernel(float* __restrict__ out) {
    int node = (blockIdx.x * blockDim.x + threadIdx.x) >> 5;
    int lane = threadIdx.x & 31;
    if (node >= N_NODES) return;

    int e0 = g_off[node];
    int e1 = g_off[node + 1];
    int deg = e1 - e0;
    if (deg == 0) return;   // agg contributes 0 (matches max(deg,1) semantics)

    // wsum: lane-parallel over edges, warp reduce
    float ws = 0.f;
    for (int e = e0 + lane; e < e1; e += 32)
        ws += __int_as_float(__ldg(&g_edges[e].y));
#pragma unroll
    for (int o = 16; o > 0; o >>= 1)
        ws += __shfl_xor_sync(0xffffffff, ws, o);

    float inv_ws  = __fdividef(1.0f, ws);
    float inv_deg = __fdividef(1.0f, (float)deg);

    float4 acc0 = make_float4(0.f, 0.f, 0.f, 0.f);
    float4 acc1 = make_float4(0.f, 0.f, 0.f, 0.f);
    const int hb = lane * 2;
    int e = e0;
    for (; e + 3 < e1; e += 4) {
        int2 r0 = __ldg(&g_edges[e]);
        int2 r1 = __ldg(&g_edges[e + 1]);
        int2 r2 = __ldg(&g_edges[e + 2]);
        int2 r3 = __ldg(&g_edges[e + 3]);
        uint2 q0 = *(const uint2*)&g_hh[r0.x * (F / 2) + hb];
        uint2 q1 = *(const uint2*)&g_hh[r1.x * (F / 2) + hb];
        uint2 q2 = *(const uint2*)&g_hh[r2.x * (F / 2) + hb];
        uint2 q3 = *(const uint2*)&g_hh[r3.x * (F / 2) + hb];
        float m0 = __expf(-__int_as_float(r0.y) * inv_ws);
        float m1 = __expf(-__int_as_float(r1.y) * inv_ws);
        float m2 = __expf(-__int_as_float(r2.y) * inv_ws);
        float m3 = __expf(-__int_as_float(r3.y) * inv_ws);
        float2 a0 = __half22float2(*(__half2*)&q0.x), b0 = __half22float2(*(__half2*)&q0.y);
        float2 a1 = __half22float2(*(__half2*)&q1.x), b1 = __half22float2(*(__half2*)&q1.y);
        float2 a2 = __half22float2(*(__half2*)&q2.x), b2 = __half22float2(*(__half2*)&q2.y);
        float2 a3 = __half22float2(*(__half2*)&q3.x), b3 = __half22float2(*(__half2*)&q3.y);
        acc0.x = fmaf(m0, a0.x, acc0.x); acc0.y = fmaf(m0, a0.y, acc0.y);
        acc0.z = fmaf(m0, b0.x, acc0.z); acc0.w = fmaf(m0, b0.y, acc0.w);
        acc1.x = fmaf(m1, a1.x, acc1.x); acc1.y = fmaf(m1, a1.y, acc1.y);
        acc1.z = fmaf(m1, b1.x, acc1.z); acc1.w = fmaf(m1, b1.y, acc1.w);
        acc0.x = fmaf(m2, a2.x, acc0.x); acc0.y = fmaf(m2, a2.y, acc0.y);
        acc0.z = fmaf(m2, b2.x, acc0.z); acc0.w = fmaf(m2, b2.y, acc0.w);
        acc1.x = fmaf(m3, a3.x, acc1.x); acc1.y = fmaf(m3, a3.y, acc1.y);
        acc1.z = fmaf(m3, b3.x, acc1.z); acc1.w = fmaf(m3, b3.y, acc1.w);
    }
    for (; e < e1; e++) {
        int2 rec = __ldg(&g_edges[e]);
        uint2 q = *(const uint2*)&g_hh[rec.x * (F / 2) + hb];
        float m = __expf(-__int_as_float(rec.y) * inv_ws);
        float2 a = __half22float2(*(__half2*)&q.x);
        float2 b = __half22float2(*(__half2*)&q.y);
        acc0.x = fmaf(m, a.x, acc0.x); acc0.y = fmaf(m, a.y, acc0.y);
        acc0.z = fmaf(m, b.x, acc0.z); acc0.w = fmaf(m, b.y, acc0.w);
    }
    acc0.x += acc1.x; acc0.y += acc1.y; acc0.z += acc1.z; acc0.w += acc1.w;

    float4 o = *(const float4*)&out[node * F + lane * 4];
    o.x += acc0.x * inv_deg;
    o.y += acc0.y * inv_deg;
    o.z += acc0.z * inv_deg;
    o.w += acc0.w * inv_deg;
    *(float4*)&out[node * F + lane * 4] = o;
}

// ---------------------------------------------------------------------------
extern "C" void kernel_launch(void* const* d_in, const int* in_sizes, int n_in,
                              void* d_out, int out_size) {
    const float* feat  = (const float*)d_in[0];
    const float* efeat = (const float*)d_in[1];
    const int*   src   = (const int*)d_in[2];
    const int*   dst   = (const int*)d_in[3];
    const float* Wp    = (const float*)d_in[4];
    const float* bp    = (const float*)d_in[5];
    const float* Ws    = (const float*)d_in[6];
    const float* bs    = (const float*)d_in[7];
    float* out = (float*)d_out;

    zero_transpose_kernel<<<(N_NODES + 255) / 256, 256>>>(Wp, Ws);
    hist_kernel<<<(N_EDGES + 255) / 256, 256>>>(dst);
    scan_kernel<<<1, 1024>>>();
    scatter_kernel<<<(N_EDGES + 255) / 256, 256>>>(efeat, src, dst);
    gemm_dual<<<(N_NODES + TM - 1) / TM, 256>>>(feat, bp, bs, out);
    agg_kernel<<<(N_NODES * 32 + 255) / 256, 256>>>(out);
}